// round 1
// baseline (speedup 1.0000x reference)
#include <cuda_runtime.h>
#include <cuda_bf16.h>
#include <cstdint>

// ============================================================
// AutoGNN: 2-layer GraphSAGE-mean + linear head, fp32.
//   Y1 = X @ W1^T          (dense GEMM, 128->128)
//   h1 = relu(mean(Y1[nbrs]))   (gather, L2-bound)
//   Y2 = h1 @ W2^T
//   h2 = relu(mean(Y2[nbrs]))
//   out = h2 @ Wlast^T     (128->40)
// Commuting mean past the matmul is exact (both linear).
// ============================================================

#define FEAT 128
#define SAMPLE 25
#define CLASSES 40
#define MAXN 100000

// scratch ping-pong buffers (51.2 MB each) — __device__ globals, no alloc
__device__ float g_Y[(size_t)MAXN * FEAT];
__device__ float g_H[(size_t)MAXN * FEAT];

// ------------------------------------------------------------
// GEMM: C[n,128] = A[n,128] @ W[128,128]^T   (W is [out][in])
// 128-row tiles, 256 threads, 8x8 thread microtile, packed f32x2 FMA.
// ------------------------------------------------------------
__global__ __launch_bounds__(256, 2) void gemm128_kernel(
    const float* __restrict__ A, const float* __restrict__ W,
    float* __restrict__ C, int n)
{
    __shared__ float As[32][132];   // [k][row], padded: stride 132 => conflict-free & 16B-aligned
    __shared__ float Ws[32][132];   // [k][col] = W[col][k]

    const int tid = threadIdx.x;
    const int m0  = blockIdx.x * 128;
    const int tr  = tid >> 4;   // row group 0..15  -> rows tr*8..+7
    const int tc  = tid & 15;   // col group 0..15  -> cols tc*8..+7

    unsigned long long acc[8][4];   // 8 rows x 4 col-pairs (f32x2 packed)
    #pragma unroll
    for (int r = 0; r < 8; r++)
        #pragma unroll
        for (int c = 0; c < 4; c++) acc[r][c] = 0ull;

    for (int kc = 0; kc < 128; kc += 32) {
        // ---- load A tile transposed: As[k][row] ----
        #pragma unroll
        for (int i = 0; i < 4; i++) {
            int t   = tid + i * 256;      // 0..1023
            int row = t >> 3;             // 0..127
            int kq  = t & 7;              // 0..7  (float4 along k)
            int grow = m0 + row;
            float4 v = make_float4(0.f, 0.f, 0.f, 0.f);
            if (grow < n)
                v = *reinterpret_cast<const float4*>(A + (size_t)grow * 128 + kc + kq * 4);
            As[kq * 4 + 0][row] = v.x;
            As[kq * 4 + 1][row] = v.y;
            As[kq * 4 + 2][row] = v.z;
            As[kq * 4 + 3][row] = v.w;
        }
        // ---- load W transposed: Ws[k][col] ----
        #pragma unroll
        for (int i = 0; i < 4; i++) {
            int t   = tid + i * 256;
            int col = t >> 3;
            int kq  = t & 7;
            float4 v = *reinterpret_cast<const float4*>(W + (size_t)col * 128 + kc + kq * 4);
            Ws[kq * 4 + 0][col] = v.x;
            Ws[kq * 4 + 1][col] = v.y;
            Ws[kq * 4 + 2][col] = v.z;
            Ws[kq * 4 + 3][col] = v.w;
        }
        __syncthreads();

        #pragma unroll
        for (int k = 0; k < 32; k++) {
            float4 a0 = *reinterpret_cast<const float4*>(&As[k][tr * 8]);
            float4 a1 = *reinterpret_cast<const float4*>(&As[k][tr * 8 + 4]);
            // w pairs come packed for free from consecutive-col layout
            ulonglong2 w01 = *reinterpret_cast<const ulonglong2*>(&Ws[k][tc * 8]);
            ulonglong2 w23 = *reinterpret_cast<const ulonglong2*>(&Ws[k][tc * 8 + 4]);
            float av[8] = {a0.x, a0.y, a0.z, a0.w, a1.x, a1.y, a1.z, a1.w};
            #pragma unroll
            for (int r = 0; r < 8; r++) {
                unsigned long long ap;
                unsigned int au = __float_as_uint(av[r]);
                asm("mov.b64 %0, {%1, %1};" : "=l"(ap) : "r"(au));
                asm("fma.rn.f32x2 %0, %1, %2, %0;" : "+l"(acc[r][0]) : "l"(ap), "l"(w01.x));
                asm("fma.rn.f32x2 %0, %1, %2, %0;" : "+l"(acc[r][1]) : "l"(ap), "l"(w01.y));
                asm("fma.rn.f32x2 %0, %1, %2, %0;" : "+l"(acc[r][2]) : "l"(ap), "l"(w23.x));
                asm("fma.rn.f32x2 %0, %1, %2, %0;" : "+l"(acc[r][3]) : "l"(ap), "l"(w23.y));
            }
        }
        __syncthreads();
    }

    // ---- epilogue ----
    const int grow0 = m0 + tr * 8;
    #pragma unroll
    for (int r = 0; r < 8; r++) {
        int grow = grow0 + r;
        if (grow < n) {
            float2 p0 = *reinterpret_cast<float2*>(&acc[r][0]);
            float2 p1 = *reinterpret_cast<float2*>(&acc[r][1]);
            float2 p2 = *reinterpret_cast<float2*>(&acc[r][2]);
            float2 p3 = *reinterpret_cast<float2*>(&acc[r][3]);
            float4 o0 = make_float4(p0.x, p0.y, p1.x, p1.y);
            float4 o1 = make_float4(p2.x, p2.y, p3.x, p3.y);
            float* crow = C + (size_t)grow * 128 + tc * 8;
            *reinterpret_cast<float4*>(crow)     = o0;
            *reinterpret_cast<float4*>(crow + 4) = o1;
        }
    }
}

// ------------------------------------------------------------
// Gather: H[i] = relu( mean_j Y[nbrs[i][j]] )   — warp per node
// One LDG.128 warp-instruction per 512B neighbor row; L2-bound.
// ------------------------------------------------------------
__global__ __launch_bounds__(256) void gather_mean_relu_kernel(
    const float* __restrict__ Y, const int* __restrict__ nbrs,
    float* __restrict__ H, int n)
{
    const int warp = (blockIdx.x * blockDim.x + threadIdx.x) >> 5;
    const int lane = threadIdx.x & 31;
    if (warp >= n) return;

    int idx = 0;
    if (lane < SAMPLE) idx = nbrs[(size_t)warp * SAMPLE + lane];

    float4 acc = make_float4(0.f, 0.f, 0.f, 0.f);
    #pragma unroll
    for (int j = 0; j < SAMPLE; j++) {
        int row = __shfl_sync(0xffffffffu, idx, j);
        float4 v = __ldg(reinterpret_cast<const float4*>(Y + (size_t)row * 128) + lane);
        acc.x += v.x; acc.y += v.y; acc.z += v.z; acc.w += v.w;
    }
    const float s = 1.0f / (float)SAMPLE;
    float4 o;
    o.x = fmaxf(acc.x * s, 0.f);
    o.y = fmaxf(acc.y * s, 0.f);
    o.z = fmaxf(acc.z * s, 0.f);
    o.w = fmaxf(acc.w * s, 0.f);
    reinterpret_cast<float4*>(H + (size_t)warp * 128)[lane] = o;
}

// ------------------------------------------------------------
// Last GEMM: out[n,40] = H[n,128] @ Wlast[40,128]^T
// Thread computes (node, 4 consecutive outputs). Wlast in padded smem.
// ------------------------------------------------------------
__global__ __launch_bounds__(256) void gemm_last_kernel(
    const float* __restrict__ H, const float* __restrict__ WL,
    float* __restrict__ out, int n)
{
    __shared__ float Ws[CLASSES * 132];   // [c][k] stride 132 -> conflict-free
    for (int i = threadIdx.x; i < CLASSES * 128; i += 256) {
        int c = i >> 7;
        int k = i & 127;
        Ws[c * 132 + k] = WL[i];
    }
    __syncthreads();

    const int g    = blockIdx.x * 256 + threadIdx.x;
    const int node = g / 10;
    const int cg   = g % 10;            // output group: cols cg*4..+3
    if (node >= n) return;

    const float4* hrow = reinterpret_cast<const float4*>(H + (size_t)node * 128);
    float acc0 = 0.f, acc1 = 0.f, acc2 = 0.f, acc3 = 0.f;
    #pragma unroll 8
    for (int k4 = 0; k4 < 32; k4++) {
        float4 hv = __ldg(hrow + k4);
        float4 w0 = *reinterpret_cast<const float4*>(&Ws[(cg * 4 + 0) * 132 + k4 * 4]);
        float4 w1 = *reinterpret_cast<const float4*>(&Ws[(cg * 4 + 1) * 132 + k4 * 4]);
        float4 w2 = *reinterpret_cast<const float4*>(&Ws[(cg * 4 + 2) * 132 + k4 * 4]);
        float4 w3 = *reinterpret_cast<const float4*>(&Ws[(cg * 4 + 3) * 132 + k4 * 4]);
        acc0 += hv.x * w0.x + hv.y * w0.y + hv.z * w0.z + hv.w * w0.w;
        acc1 += hv.x * w1.x + hv.y * w1.y + hv.z * w1.z + hv.w * w1.w;
        acc2 += hv.x * w2.x + hv.y * w2.y + hv.z * w2.z + hv.w * w2.w;
        acc3 += hv.x * w3.x + hv.y * w3.y + hv.z * w3.z + hv.w * w3.w;
    }
    *reinterpret_cast<float4*>(out + (size_t)node * CLASSES + cg * 4) =
        make_float4(acc0, acc1, acc2, acc3);
}

// ------------------------------------------------------------
extern "C" void kernel_launch(void* const* d_in, const int* in_sizes, int n_in,
                              void* d_out, int out_size)
{
    const float* X    = (const float*)d_in[0];   // [N,128]
    const int*   nbrs = (const int*)  d_in[1];   // [N,25]
    const float* W1   = (const float*)d_in[2];   // [128,128]
    const float* W2   = (const float*)d_in[3];   // [128,128]
    const float* WL   = (const float*)d_in[4];   // [40,128]
    float*       out  = (float*)d_out;

    const int n = in_sizes[1] / SAMPLE;

    float *Y = nullptr, *H = nullptr;
    cudaGetSymbolAddress((void**)&Y, g_Y);
    cudaGetSymbolAddress((void**)&H, g_H);

    const int gemm_grid   = (n + 127) / 128;
    const int gather_grid = (n + 7) / 8;           // 8 warps / CTA
    const int last_grid   = (n * 10 + 255) / 256;

    gemm128_kernel<<<gemm_grid, 256>>>(X, W1, Y, n);          // Y1
    gather_mean_relu_kernel<<<gather_grid, 256>>>(Y, nbrs, H, n); // h1
    gemm128_kernel<<<gemm_grid, 256>>>(H, W2, Y, n);          // Y2
    gather_mean_relu_kernel<<<gather_grid, 256>>>(Y, nbrs, H, n); // h2
    gemm_last_kernel<<<last_grid, 256>>>(H, WL, out, n);      // out
}

// round 3
// speedup vs baseline: 2.1277x; 2.1277x over previous
#include <cuda_runtime.h>
#include <cuda_bf16.h>
#include <cstdint>

// ================================================================
// AutoGNN: mma.sync (bf16 hi/lo split, fp32 accum) + L2-bound gathers.
//   split X -> (Xhi,Xlo)
//   Y1 = X @ W1^T        (HMMA, 3-term split)
//   h1 = relu(mean(Y1[nbrs])) -> (hi,lo)
//   Y2 = h1 @ W2^T
//   h2 = relu(mean(Y2[nbrs])) -> (hi,lo)
//   out = h2 @ Wlast^T   (Wlast rows padded 40->64)
// NOTE: harness builds via plain compute_103 PTX -> no tcgen05;
// mma.sync/ldmatrix are baseline PTX and compile fine.
// ================================================================

#define FEAT 128
#define SAMPLE 25
#define CLASSES 40
#define MAXN 100000

__device__ __nv_bfloat16 g_Ahi[(size_t)MAXN * FEAT];
__device__ __nv_bfloat16 g_Alo[(size_t)MAXN * FEAT];
__device__ float         g_Y  [(size_t)MAXN * FEAT];
__device__ __nv_bfloat16 g_W1hi[128 * 128], g_W1lo[128 * 128];
__device__ __nv_bfloat16 g_W2hi[128 * 128], g_W2lo[128 * 128];
__device__ __nv_bfloat16 g_WLhi[64 * 128],  g_WLlo[64 * 128];

__device__ __forceinline__ uint32_t smem_u32(const void* p) {
    uint32_t a;
    asm("{ .reg .u64 t; cvta.to.shared.u64 t, %1; cvt.u32.u64 %0, t; }" : "=r"(a) : "l"(p));
    return a;
}

__device__ __forceinline__ void ldsm4(uint32_t addr, uint32_t& r0, uint32_t& r1,
                                      uint32_t& r2, uint32_t& r3) {
    asm volatile("ldmatrix.sync.aligned.m8n8.x4.shared.b16 {%0,%1,%2,%3}, [%4];"
                 : "=r"(r0), "=r"(r1), "=r"(r2), "=r"(r3) : "r"(addr));
}

__device__ __forceinline__ void mma_bf16(float* c, const uint32_t* a,
                                         uint32_t b0, uint32_t b1) {
    asm volatile(
        "mma.sync.aligned.m16n8k16.row.col.f32.bf16.bf16.f32 "
        "{%0,%1,%2,%3}, {%4,%5,%6,%7}, {%8,%9}, {%0,%1,%2,%3};"
        : "+f"(c[0]), "+f"(c[1]), "+f"(c[2]), "+f"(c[3])
        : "r"(a[0]), "r"(a[1]), "r"(a[2]), "r"(a[3]), "r"(b0), "r"(b1));
}

// ================================================================
// GEMM: C[128/CTA rows, CST] = (Ahi+Alo) @ (Whi+Wlo)^T
// NOUT: padded W rows (128 or 64). smem row stride 272B (136 bf16)
// -> 8 ldmatrix rows at 272B stride hit distinct 16B segments.
// ================================================================
template<int NOUT, int CST>
__global__ __launch_bounds__(256, 1) void gemm_mma_kernel(
    const __nv_bfloat16* __restrict__ Ahi, const __nv_bfloat16* __restrict__ Alo,
    const __nv_bfloat16* __restrict__ Whi, const __nv_bfloat16* __restrict__ Wlo,
    float* __restrict__ C, int n)
{
    extern __shared__ char smem[];
    constexpr int RS = 272;                 // bytes per smem row (136 bf16)
    constexpr int OFF_AHI = 0;
    constexpr int OFF_ALO = OFF_AHI + 128 * RS;
    constexpr int OFF_WHI = OFF_ALO + 128 * RS;
    constexpr int OFF_WLO = OFF_WHI + NOUT * RS;
    constexpr int WN = NOUT / 2;            // warp n-extent (64 or 32)
    constexpr int NT = WN / 8;              // n8 tiles per warp (8 or 4)

    const int tid  = threadIdx.x;
    const int wid  = tid >> 5;
    const int lane = tid & 31;
    const int wm   = wid >> 1;              // 0..3 -> m offset wm*32
    const int wn   = wid & 1;               // 0..1 -> n offset wn*WN
    const int m0   = blockIdx.x * 128;

    // ---- load A (hi/lo): 128 rows x 128 bf16 each ----
    #pragma unroll
    for (int i = 0; i < 8; i++) {
        int t = i * 256 + tid;              // 2048 uint4
        int row = t >> 4;
        int c16 = t & 15;
        int grow = m0 + row;
        uint4 vh = make_uint4(0, 0, 0, 0), vl = make_uint4(0, 0, 0, 0);
        if (grow < n) {
            size_t g = (size_t)grow * 128 + c16 * 8;
            vh = *reinterpret_cast<const uint4*>(Ahi + g);
            vl = *reinterpret_cast<const uint4*>(Alo + g);
        }
        int off = row * RS + c16 * 16;
        *reinterpret_cast<uint4*>(smem + OFF_AHI + off) = vh;
        *reinterpret_cast<uint4*>(smem + OFF_ALO + off) = vl;
    }
    // ---- load W (hi/lo): NOUT rows x 128 bf16 ----
    #pragma unroll
    for (int i = 0; i < NOUT / 16; i++) {
        int t = i * 256 + tid;
        int row = t >> 4;
        int c16 = t & 15;
        size_t g = (size_t)row * 128 + c16 * 8;
        int off = row * RS + c16 * 16;
        *reinterpret_cast<uint4*>(smem + OFF_WHI + off) =
            *reinterpret_cast<const uint4*>(Whi + g);
        *reinterpret_cast<uint4*>(smem + OFF_WLO + off) =
            *reinterpret_cast<const uint4*>(Wlo + g);
    }
    __syncthreads();

    const uint32_t sb = smem_u32(smem);
    const uint32_t aBase[3] = { sb + OFF_AHI, sb + OFF_AHI, sb + OFF_ALO };
    const uint32_t wBase[3] = { sb + OFF_WHI, sb + OFF_WLO, sb + OFF_WHI };

    // lane-derived ldmatrix offsets
    const int l15   = lane & 15;
    const int aHalf = (lane & 16) ? 16 : 0;               // k half (8 bf16 = 16B)
    const uint32_t aRow0 = (uint32_t)((wm * 32 + l15) * RS + aHalf);
    const uint32_t aRow1 = aRow0 + 16 * RS;
    const int bRow  = (lane & 7) + ((lane & 16) ? 8 : 0);
    const int bHalf = (lane & 8) ? 16 : 0;
    uint32_t bRowByte[NT / 2];
    #pragma unroll
    for (int jp = 0; jp < NT / 2; jp++)
        bRowByte[jp] = (uint32_t)((wn * WN + jp * 16 + bRow) * RS + bHalf);

    float c[2][NT][4];
    #pragma unroll
    for (int mt = 0; mt < 2; mt++)
        #pragma unroll
        for (int j = 0; j < NT; j++)
            #pragma unroll
            for (int q = 0; q < 4; q++) c[mt][j][q] = 0.f;

    #pragma unroll
    for (int s = 0; s < 3; s++) {
        #pragma unroll
        for (int ks = 0; ks < 8; ks++) {
            const uint32_t kb = ks * 32;
            uint32_t a[2][4];
            ldsm4(aBase[s] + aRow0 + kb, a[0][0], a[0][1], a[0][2], a[0][3]);
            ldsm4(aBase[s] + aRow1 + kb, a[1][0], a[1][1], a[1][2], a[1][3]);
            uint32_t b[NT][2];
            #pragma unroll
            for (int jp = 0; jp < NT / 2; jp++)
                ldsm4(wBase[s] + bRowByte[jp] + kb,
                      b[2 * jp][0], b[2 * jp][1], b[2 * jp + 1][0], b[2 * jp + 1][1]);
            #pragma unroll
            for (int mt = 0; mt < 2; mt++)
                #pragma unroll
                for (int j = 0; j < NT; j++)
                    mma_bf16(c[mt][j], a[mt], b[j][0], b[j][1]);
        }
    }

    // ---- epilogue: fragment scatter to gmem ----
    const int qrow = lane >> 2;             // 0..7
    const int qcol = (lane & 3) * 2;
    #pragma unroll
    for (int mt = 0; mt < 2; mt++) {
        #pragma unroll
        for (int half = 0; half < 2; half++) {
            int m_g = m0 + wm * 32 + mt * 16 + qrow + half * 8;
            if (m_g < n) {
                float* crow = C + (size_t)m_g * CST;
                #pragma unroll
                for (int j = 0; j < NT; j++) {
                    int n_g = wn * WN + j * 8 + qcol;
                    if (CST == 128 || n_g < CST) {
                        float2 v = make_float2(c[mt][j][half * 2], c[mt][j][half * 2 + 1]);
                        *reinterpret_cast<float2*>(crow + n_g) = v;
                    }
                }
            }
        }
    }
}

// ================================================================
// Gather: (Hhi,Hlo) = split( relu( mean_j Y[nbrs[i][j]] ) )
// ================================================================
__global__ __launch_bounds__(256) void gather_split_kernel(
    const float* __restrict__ Y, const int* __restrict__ nbrs,
    __nv_bfloat16* __restrict__ Hhi, __nv_bfloat16* __restrict__ Hlo, int n)
{
    const int warp = (blockIdx.x * blockDim.x + threadIdx.x) >> 5;
    const int lane = threadIdx.x & 31;
    if (warp >= n) return;

    int idx = 0;
    if (lane < SAMPLE) idx = nbrs[(size_t)warp * SAMPLE + lane];

    float4 acc = make_float4(0.f, 0.f, 0.f, 0.f);
    #pragma unroll
    for (int j = 0; j < SAMPLE; j++) {
        int row = __shfl_sync(0xffffffffu, idx, j);
        float4 v = __ldg(reinterpret_cast<const float4*>(Y + (size_t)row * 128) + lane);
        acc.x += v.x; acc.y += v.y; acc.z += v.z; acc.w += v.w;
    }
    const float s = 1.0f / (float)SAMPLE;
    float o[4] = { fmaxf(acc.x * s, 0.f), fmaxf(acc.y * s, 0.f),
                   fmaxf(acc.z * s, 0.f), fmaxf(acc.w * s, 0.f) };
    __nv_bfloat16 h[4], l[4];
    #pragma unroll
    for (int q = 0; q < 4; q++) {
        h[q] = __float2bfloat16(o[q]);
        l[q] = __float2bfloat16(o[q] - __bfloat162float(h[q]));
    }
    *(reinterpret_cast<uint2*>(Hhi + (size_t)warp * 128) + lane) =
        *reinterpret_cast<uint2*>(h);
    *(reinterpret_cast<uint2*>(Hlo + (size_t)warp * 128) + lane) =
        *reinterpret_cast<uint2*>(l);
}

// ================================================================
// Splitters
// ================================================================
__global__ void split_x_kernel(const float* __restrict__ X,
                               __nv_bfloat16* __restrict__ hi,
                               __nv_bfloat16* __restrict__ lo, int total4)
{
    int i = blockIdx.x * blockDim.x + threadIdx.x;
    if (i >= total4) return;
    float4 v = __ldg(reinterpret_cast<const float4*>(X) + i);
    float f[4] = { v.x, v.y, v.z, v.w };
    __nv_bfloat16 h[4], l[4];
    #pragma unroll
    for (int q = 0; q < 4; q++) {
        h[q] = __float2bfloat16(f[q]);
        l[q] = __float2bfloat16(f[q] - __bfloat162float(h[q]));
    }
    *(reinterpret_cast<uint2*>(hi) + i) = *reinterpret_cast<uint2*>(h);
    *(reinterpret_cast<uint2*>(lo) + i) = *reinterpret_cast<uint2*>(l);
}

__global__ void split_w_kernel(const float* __restrict__ W1,
                               const float* __restrict__ W2,
                               const float* __restrict__ WL,
                               __nv_bfloat16* w1h, __nv_bfloat16* w1l,
                               __nv_bfloat16* w2h, __nv_bfloat16* w2l,
                               __nv_bfloat16* wlh, __nv_bfloat16* wll)
{
    int i = blockIdx.x * blockDim.x + threadIdx.x;  // 0 .. 40959
    float v; __nv_bfloat16 *ph, *pl; int idx;
    if (i < 16384)      { v = W1[i];            ph = w1h; pl = w1l; idx = i; }
    else if (i < 32768) { idx = i - 16384; v = W2[idx]; ph = w2h; pl = w2l; }
    else if (i < 40960) {
        idx = i - 32768;                 // 0..8191 over padded [64][128]
        int row = idx >> 7;
        v = (row < CLASSES) ? WL[idx] : 0.f;
        ph = wlh; pl = wll;
    } else return;
    __nv_bfloat16 h = __float2bfloat16(v);
    ph[idx] = h;
    pl[idx] = __float2bfloat16(v - __bfloat162float(h));
}

// ================================================================
extern "C" void kernel_launch(void* const* d_in, const int* in_sizes, int n_in,
                              void* d_out, int out_size)
{
    const float* X    = (const float*)d_in[0];
    const int*   nbrs = (const int*)  d_in[1];
    const float* W1   = (const float*)d_in[2];
    const float* W2   = (const float*)d_in[3];
    const float* WL   = (const float*)d_in[4];
    float*       out  = (float*)d_out;
    const int n = in_sizes[1] / SAMPLE;

    __nv_bfloat16 *Ahi, *Alo, *w1h, *w1l, *w2h, *w2l, *wlh, *wll;
    float* Y;
    cudaGetSymbolAddress((void**)&Ahi, g_Ahi);
    cudaGetSymbolAddress((void**)&Alo, g_Alo);
    cudaGetSymbolAddress((void**)&Y,   g_Y);
    cudaGetSymbolAddress((void**)&w1h, g_W1hi);
    cudaGetSymbolAddress((void**)&w1l, g_W1lo);
    cudaGetSymbolAddress((void**)&w2h, g_W2hi);
    cudaGetSymbolAddress((void**)&w2l, g_W2lo);
    cudaGetSymbolAddress((void**)&wlh, g_WLhi);
    cudaGetSymbolAddress((void**)&wll, g_WLlo);

    const int SM128 = 272 * (2 * 128 + 2 * 128);   // 139264
    const int SM64  = 272 * (2 * 128 + 2 * 64);    // 104448
    cudaFuncSetAttribute(gemm_mma_kernel<128, 128>,
                         cudaFuncAttributeMaxDynamicSharedMemorySize, SM128);
    cudaFuncSetAttribute(gemm_mma_kernel<64, 40>,
                         cudaFuncAttributeMaxDynamicSharedMemorySize, SM64);

    const int gg = (n + 127) / 128;
    const int sg = (n * 32 + 255) / 256;
    const int ag = (n + 7) / 8;

    split_w_kernel<<<160, 256>>>(W1, W2, WL, w1h, w1l, w2h, w2l, wlh, wll);
    split_x_kernel<<<sg, 256>>>(X, Ahi, Alo, n * 32);
    gemm_mma_kernel<128, 128><<<gg, 256, SM128>>>(Ahi, Alo, w1h, w1l, Y, n);
    gather_split_kernel<<<ag, 256>>>(Y, nbrs, Ahi, Alo, n);
    gemm_mma_kernel<128, 128><<<gg, 256, SM128>>>(Ahi, Alo, w2h, w2l, Y, n);
    gather_split_kernel<<<ag, 256>>>(Y, nbrs, Ahi, Alo, n);
    gemm_mma_kernel<64, 40><<<gg, 256, SM64>>>(Ahi, Alo, wlh, wll, out, n);
}